// round 1
// baseline (speedup 1.0000x reference)
#include <cuda_runtime.h>

#define NN 100000
#define NE 1600000

// ---------------- scratch (device globals; no allocation allowed) -------------
__device__ float g_z1[(size_t)NN * 256]; // [x@W1l | x@W1r]
__device__ float g_h [(size_t)NN * 128]; // relu(layer1)
__device__ float g_z2[(size_t)NN * 128]; // [h@W2l | h@W2r]
__device__ float g_w1[128 * 256];        // concat(W1l, W1r)
__device__ float g_w2[128 * 128];        // concat(W2l, W2r)
__device__ int   g_deg[NN];
__device__ int   g_rowptr[NN];
__device__ int   g_pos[NN];
__device__ int   g_csr[NE];              // src ids grouped by dst
__device__ int   g_bsum[128];

// ---------------- weight concat ----------------------------------------------
__global__ void k_concat_w1(const float* __restrict__ Wl, const float* __restrict__ Wr) {
    int i = blockIdx.x * 256 + threadIdx.x;
    if (i < 128 * 128) {
        int d = i >> 7, h = i & 127;
        g_w1[d * 256 + h]       = Wl[i];
        g_w1[d * 256 + 128 + h] = Wr[i];
    }
}
__global__ void k_concat_w2(const float* __restrict__ Wl, const float* __restrict__ Wr) {
    int i = blockIdx.x * 256 + threadIdx.x;
    if (i < 128 * 64) {
        int k = i >> 6, o = i & 63;
        g_w2[k * 128 + o]      = Wl[i];
        g_w2[k * 128 + 64 + o] = Wr[i];
    }
}

// ---------------- CSR build ---------------------------------------------------
__global__ void k_zero_deg() {
    int i = blockIdx.x * 256 + threadIdx.x;
    if (i < NN) g_deg[i] = 0;
}
__global__ void k_hist(const int* __restrict__ dst) {
    int e = blockIdx.x * 256 + threadIdx.x;
    if (e < NE) atomicAdd(&g_deg[dst[e]], 1);
}
__global__ void k_scan1() {
    __shared__ int sm[1024];
    int t = threadIdx.x;
    int i = blockIdx.x * 1024 + t;
    int v = (i < NN) ? g_deg[i] : 0;
    sm[t] = v;
    __syncthreads();
    for (int off = 1; off < 1024; off <<= 1) {
        int tmp = (t >= off) ? sm[t - off] : 0;
        __syncthreads();
        sm[t] += tmp;
        __syncthreads();
    }
    if (i < NN) g_rowptr[i] = sm[t] - v; // exclusive
    if (t == 1023) g_bsum[blockIdx.x] = sm[1023];
}
__global__ void k_scan2(int nb) {
    if (threadIdx.x == 0) {
        int acc = 0;
        for (int b = 0; b < nb; b++) { int tv = g_bsum[b]; g_bsum[b] = acc; acc += tv; }
    }
}
__global__ void k_scan3() {
    int i = blockIdx.x * 256 + threadIdx.x;
    if (i < NN) {
        int v = g_rowptr[i] + g_bsum[i >> 10];
        g_rowptr[i] = v;
        g_pos[i]    = v;
    }
}
__global__ void k_fill(const int* __restrict__ src, const int* __restrict__ dst) {
    int e = blockIdx.x * 256 + threadIdx.x;
    if (e < NE) {
        int idx = atomicAdd(&g_pos[dst[e]], 1);
        g_csr[idx] = src[e];
    }
}

// ---------------- SGEMM: C[M,Nc] = A[M,128] * B[128,Nc] ----------------------
__global__ __launch_bounds__(256, 2) void k_sgemm(
    int M, int Nc,
    const float* __restrict__ A, const float* __restrict__ B, float* __restrict__ C)
{
    const int K = 128, BM = 128, BN = 128, BK = 8;
    __shared__ __align__(16) float As[BK][BM];
    __shared__ __align__(16) float Bs[BK][BN];
    int tid = threadIdx.x;
    int blockRow = blockIdx.y * BM, blockCol = blockIdx.x * BN;
    int trow = (tid >> 4) * 8, tcol = (tid & 15) * 8;
    float acc[8][8];
#pragma unroll
    for (int i = 0; i < 8; i++)
#pragma unroll
        for (int j = 0; j < 8; j++) acc[i][j] = 0.f;

    int aRow = tid >> 1, aCol = (tid & 1) * 4;   // A tile 128x8, float4 per thread
    int bRow = tid >> 5, bCol = (tid & 31) * 4;  // B tile 8x128, float4 per thread

    for (int k0 = 0; k0 < K; k0 += BK) {
        int gRow = blockRow + aRow;
        float4 av = make_float4(0.f, 0.f, 0.f, 0.f);
        if (gRow < M) av = *(const float4*)(A + (size_t)gRow * K + k0 + aCol);
        As[aCol + 0][aRow] = av.x;
        As[aCol + 1][aRow] = av.y;
        As[aCol + 2][aRow] = av.z;
        As[aCol + 3][aRow] = av.w;
        float4 bv = *(const float4*)(B + (size_t)(k0 + bRow) * Nc + blockCol + bCol);
        *(float4*)&Bs[bRow][bCol] = bv;
        __syncthreads();
#pragma unroll
        for (int k = 0; k < BK; k++) {
            float4 a0 = *(const float4*)&As[k][trow];
            float4 a1 = *(const float4*)&As[k][trow + 4];
            float4 b0 = *(const float4*)&Bs[k][tcol];
            float4 b1 = *(const float4*)&Bs[k][tcol + 4];
            float ar[8] = {a0.x, a0.y, a0.z, a0.w, a1.x, a1.y, a1.z, a1.w};
            float br[8] = {b0.x, b0.y, b0.z, b0.w, b1.x, b1.y, b1.z, b1.w};
#pragma unroll
            for (int i = 0; i < 8; i++)
#pragma unroll
                for (int j = 0; j < 8; j++) acc[i][j] = fmaf(ar[i], br[j], acc[i][j]);
        }
        __syncthreads();
    }
#pragma unroll
    for (int i = 0; i < 8; i++) {
        int gRow = blockRow + trow + i;
        if (gRow < M) {
            float* Cp = C + (size_t)gRow * Nc + blockCol + tcol;
            *(float4*)Cp       = make_float4(acc[i][0], acc[i][1], acc[i][2], acc[i][3]);
            *(float4*)(Cp + 4) = make_float4(acc[i][4], acc[i][5], acc[i][6], acc[i][7]);
        }
    }
}

// ---------------- pull-mode mean aggregation ---------------------------------
// layer 1: h[i] = relu( mean_j z1[j,0:128] + b1 + z1[i,128:256] )
__global__ void k_agg1(const float* __restrict__ b1) {
    int gt = blockIdx.x * blockDim.x + threadIdx.x;
    int w = gt >> 5, lane = gt & 31;
    if (w >= NN) return;
    int start = g_rowptr[w], deg = g_deg[w];
    float4 acc = make_float4(0.f, 0.f, 0.f, 0.f);
    for (int e = 0; e < deg; e++) {
        int s = g_csr[start + e];
        float4 v = *(const float4*)(g_z1 + (size_t)s * 256 + lane * 4);
        acc.x += v.x; acc.y += v.y; acc.z += v.z; acc.w += v.w;
    }
    float inv = 1.f / (float)(deg > 0 ? deg : 1);
    float4 r  = *(const float4*)(g_z1 + (size_t)w * 256 + 128 + lane * 4);
    float4 bb = *(const float4*)(b1 + lane * 4);
    float4 o;
    o.x = fmaxf(fmaf(acc.x, inv, bb.x + r.x), 0.f);
    o.y = fmaxf(fmaf(acc.y, inv, bb.y + r.y), 0.f);
    o.z = fmaxf(fmaf(acc.z, inv, bb.z + r.z), 0.f);
    o.w = fmaxf(fmaf(acc.w, inv, bb.w + r.w), 0.f);
    *(float4*)(g_h + (size_t)w * 128 + lane * 4) = o;
}

// layer 2: out[i] = mean_j z2[j,0:64] + b2 + z2[i,64:128]
__global__ void k_agg2(const float* __restrict__ b2, float* __restrict__ out) {
    int gt = blockIdx.x * blockDim.x + threadIdx.x;
    int w = gt >> 5, lane = gt & 31;
    if (w >= NN) return;
    int start = g_rowptr[w], deg = g_deg[w];
    float2 acc = make_float2(0.f, 0.f);
    for (int e = 0; e < deg; e++) {
        int s = g_csr[start + e];
        float2 v = *(const float2*)(g_z2 + (size_t)s * 128 + lane * 2);
        acc.x += v.x; acc.y += v.y;
    }
    float inv = 1.f / (float)(deg > 0 ? deg : 1);
    float2 r = *(const float2*)(g_z2 + (size_t)w * 128 + 64 + lane * 2);
    float2 o;
    o.x = fmaf(acc.x, inv, b2[lane * 2 + 0] + r.x);
    o.y = fmaf(acc.y, inv, b2[lane * 2 + 1] + r.y);
    *(float2*)(out + (size_t)w * 64 + lane * 2) = o;
}

// ---------------- launch ------------------------------------------------------
extern "C" void kernel_launch(void* const* d_in, const int* in_sizes, int n_in,
                              void* d_out, int out_size)
{
    const float* x   = (const float*)d_in[0];
    const int*   ei  = (const int*)d_in[1];
    const float* W1l = (const float*)d_in[2];
    const float* b1  = (const float*)d_in[3];
    const float* W1r = (const float*)d_in[4];
    const float* W2l = (const float*)d_in[5];
    const float* b2  = (const float*)d_in[6];
    const float* W2r = (const float*)d_in[7];
    float* out = (float*)d_out;
    const int* src = ei;        // edge_index[0]
    const int* dst = ei + NE;   // edge_index[1]

    float *z1, *h, *z2, *w1, *w2;
    cudaGetSymbolAddress((void**)&z1, g_z1);
    cudaGetSymbolAddress((void**)&h,  g_h);
    cudaGetSymbolAddress((void**)&z2, g_z2);
    cudaGetSymbolAddress((void**)&w1, g_w1);
    cudaGetSymbolAddress((void**)&w2, g_w2);

    // weights
    k_concat_w1<<<(128 * 128 + 255) / 256, 256>>>(W1l, W1r);
    k_concat_w2<<<(128 * 64 + 255) / 256, 256>>>(W2l, W2r);

    // CSR build (per call; deterministic up to fp sum order)
    k_zero_deg<<<(NN + 255) / 256, 256>>>();
    k_hist<<<(NE + 255) / 256, 256>>>(dst);
    int nb = (NN + 1023) / 1024;
    k_scan1<<<nb, 1024>>>();
    k_scan2<<<1, 32>>>(nb);
    k_scan3<<<(NN + 255) / 256, 256>>>();
    k_fill<<<(NE + 255) / 256, 256>>>(src, dst);

    // layer 1: z1 = x @ [W1l | W1r], then pull-mean + bias + relu
    dim3 g1(2, (NN + 127) / 128);
    k_sgemm<<<g1, 256>>>(NN, 256, x, w1, z1);
    k_agg1<<<(NN * 32 + 255) / 256, 256>>>(b1);

    // layer 2: z2 = h @ [W2l | W2r], then pull-mean + bias
    dim3 g2(1, (NN + 127) / 128);
    k_sgemm<<<g2, 256>>>(NN, 128, h, w2, z2);
    k_agg2<<<(NN * 32 + 255) / 256, 256>>>(b2, out);
}

// round 5
// speedup vs baseline: 1.2438x; 1.2438x over previous
#include <cuda_runtime.h>
#include <cuda_bf16.h>
#include <cstdint>

#define NN 100000
#define NE 1600000

// ---------------- scratch (device globals; no allocation allowed) -------------
__device__ float g_z1[(size_t)NN * 256]; // [x@W1l | x@W1r]
__device__ float g_h [(size_t)NN * 128]; // relu(layer1)
__device__ float g_z2[(size_t)NN * 128]; // [h@W2l | h@W2r]
__device__ __nv_bfloat16 g_w1h[256 * 128]; // W1 concat, transposed [h',d], hi
__device__ __nv_bfloat16 g_w1l[256 * 128]; // lo
__device__ __nv_bfloat16 g_w2h[128 * 128];
__device__ __nv_bfloat16 g_w2l[128 * 128];
__device__ int   g_deg[NN];
__device__ int   g_rowptr[NN];
__device__ int   g_pos[NN];
__device__ int   g_csr[NE];
__device__ int   g_bsum[128];

// ---------------- helpers ------------------------------------------------------
__device__ __forceinline__ uint32_t smem_u32(const void* p) {
    uint32_t a;
    asm("{ .reg .u64 t; cvta.to.shared.u64 t, %1; cvt.u32.u64 %0, t; }" : "=r"(a) : "l"(p));
    return a;
}
#define LDSM_X4(r0, r1, r2, r3, a) \
    asm volatile("ldmatrix.sync.aligned.m8n8.x4.shared.b16 {%0,%1,%2,%3}, [%4];" \
        : "=r"(r0), "=r"(r1), "=r"(r2), "=r"(r3) : "r"(a))
#define MMA16816(c, a, b0, b1) \
    asm volatile("mma.sync.aligned.m16n8k16.row.col.f32.bf16.bf16.f32 " \
        "{%0,%1,%2,%3}, {%4,%5,%6,%7}, {%8,%9}, {%0,%1,%2,%3};" \
        : "+f"((c)[0]), "+f"((c)[1]), "+f"((c)[2]), "+f"((c)[3]) \
        : "r"((a)[0]), "r"((a)[1]), "r"((a)[2]), "r"((a)[3]), "r"(b0), "r"(b1))

// ---------------- weight prep: concat + transpose + bf16 hi/lo split ----------
__global__ void k_prep_w1(const float* __restrict__ Wl, const float* __restrict__ Wr) {
    int i = blockIdx.x * 256 + threadIdx.x;          // i = hp*128 + d
    if (i < 256 * 128) {
        int hp = i >> 7, d = i & 127;
        float v = (hp < 128) ? Wl[d * 128 + hp] : Wr[d * 128 + (hp - 128)];
        __nv_bfloat16 h = __float2bfloat16(v);
        __nv_bfloat16 l = __float2bfloat16(v - __bfloat162float(h));
        g_w1h[i] = h; g_w1l[i] = l;
    }
}
__global__ void k_prep_w2(const float* __restrict__ Wl, const float* __restrict__ Wr) {
    int i = blockIdx.x * 256 + threadIdx.x;          // i = op*128 + k
    if (i < 128 * 128) {
        int op = i >> 7, k = i & 127;
        float v = (op < 64) ? Wl[k * 64 + op] : Wr[k * 64 + (op - 64)];
        __nv_bfloat16 h = __float2bfloat16(v);
        __nv_bfloat16 l = __float2bfloat16(v - __bfloat162float(h));
        g_w2h[i] = h; g_w2l[i] = l;
    }
}

// ---------------- CSR build ---------------------------------------------------
__global__ void k_zero_deg() {
    int i = blockIdx.x * 256 + threadIdx.x;
    if (i < NN) g_deg[i] = 0;
}
__global__ void k_hist(const int* __restrict__ dst) {
    int e = blockIdx.x * 256 + threadIdx.x;
    if (e < NE) atomicAdd(&g_deg[dst[e]], 1);
}
__global__ void k_scan1() {
    __shared__ int sm[1024];
    int t = threadIdx.x;
    int i = blockIdx.x * 1024 + t;
    int v = (i < NN) ? g_deg[i] : 0;
    sm[t] = v;
    __syncthreads();
    for (int off = 1; off < 1024; off <<= 1) {
        int tmp = (t >= off) ? sm[t - off] : 0;
        __syncthreads();
        sm[t] += tmp;
        __syncthreads();
    }
    if (i < NN) g_rowptr[i] = sm[t] - v;
    if (t == 1023) g_bsum[blockIdx.x] = sm[1023];
}
__global__ void k_scan2(int nb) {
    if (threadIdx.x == 0) {
        int acc = 0;
        for (int b = 0; b < nb; b++) { int tv = g_bsum[b]; g_bsum[b] = acc; acc += tv; }
    }
}
__global__ void k_scan3() {
    int i = blockIdx.x * 256 + threadIdx.x;
    if (i < NN) {
        int v = g_rowptr[i] + g_bsum[i >> 10];
        g_rowptr[i] = v;
        g_pos[i]    = v;
    }
}
__global__ void k_fill(const int* __restrict__ src, const int* __restrict__ dst) {
    int e = blockIdx.x * 256 + threadIdx.x;
    if (e < NE) {
        int idx = atomicAdd(&g_pos[dst[e]], 1);
        g_csr[idx] = src[e];
    }
}

// ---------------- mma.sync split-bf16 GEMM ------------------------------------
// C[128-tile rows, 128-tile cols] = A[M x 128] fp32 * B^T  (B: [Ntot x 128] bf16)
// SMEM: 4 matrices of 128 rows x 136 bf16 (pad 8 -> 272B rows, LDSM conflict-free)
#define SPAD   136
#define SMATB  (128 * SPAD * 2)            // 34816 bytes per matrix
#define SMEM_TOT (4 * SMATB)               // 139264

__global__ __launch_bounds__(256, 1) void k_gemm_mma(
    const float* __restrict__ A, int M, int ldc,
    const __nv_bfloat16* __restrict__ Bh, const __nv_bfloat16* __restrict__ Bl,
    float* __restrict__ C)
{
    extern __shared__ __align__(16) char smem[];
    uint32_t s0 = smem_u32(smem);
    const uint32_t sa_hi = s0, sa_lo = s0 + SMATB;
    const uint32_t sb_hi = s0 + 2 * SMATB, sb_lo = s0 + 3 * SMATB;

    int tid = threadIdx.x, lane = tid & 31, wid = tid >> 5;
    int row = tid >> 1, half = tid & 1;      // 2 threads per tile-row, 64 cols each

    // --- A tile: fp32 -> bf16 hi/lo -> padded smem ---
    {
        int gRow = blockIdx.y * 128 + row;
        bool valid = gRow < M;
        const float4* Ar = (const float4*)(A + (size_t)gRow * 128 + half * 64);
        uint32_t base = (uint32_t)(row * SPAD + half * 64) * 2;
#pragma unroll
        for (int j = 0; j < 8; j++) {        // 8 floats per iter
            float4 v0 = make_float4(0.f, 0.f, 0.f, 0.f), v1 = v0;
            if (valid) { v0 = Ar[j * 2]; v1 = Ar[j * 2 + 1]; }
            float2 p[4] = {{v0.x, v0.y}, {v0.z, v0.w}, {v1.x, v1.y}, {v1.z, v1.w}};
            uint32_t hw[4], lw[4];
#pragma unroll
            for (int q = 0; q < 4; q++) {
                __nv_bfloat162 hh = __floats2bfloat162_rn(p[q].x, p[q].y);
                float2 hf = __bfloat1622float2(hh);
                __nv_bfloat162 ll = __floats2bfloat162_rn(p[q].x - hf.x, p[q].y - hf.y);
                hw[q] = *(uint32_t*)&hh;
                lw[q] = *(uint32_t*)&ll;
            }
            uint32_t a = base + j * 16;
            asm volatile("st.shared.v4.b32 [%0], {%1,%2,%3,%4};" :: "r"(sa_hi + a),
                "r"(hw[0]), "r"(hw[1]), "r"(hw[2]), "r"(hw[3]) : "memory");
            asm volatile("st.shared.v4.b32 [%0], {%1,%2,%3,%4};" :: "r"(sa_lo + a),
                "r"(lw[0]), "r"(lw[1]), "r"(lw[2]), "r"(lw[3]) : "memory");
        }
    }
    // --- B tile: bf16 hi/lo from global -> padded smem ---
    {
        size_t nRow = (size_t)(blockIdx.x * 128 + row);
        const uint4* Bhr = (const uint4*)(Bh + nRow * 128 + half * 64);
        const uint4* Blr = (const uint4*)(Bl + nRow * 128 + half * 64);
        uint32_t base = (uint32_t)(row * SPAD + half * 64) * 2;
#pragma unroll
        for (int j = 0; j < 8; j++) {
            uint4 bh = Bhr[j], bl = Blr[j];
            uint32_t a = base + j * 16;
            asm volatile("st.shared.v4.b32 [%0], {%1,%2,%3,%4};" :: "r"(sb_hi + a),
                "r"(bh.x), "r"(bh.y), "r"(bh.z), "r"(bh.w) : "memory");
            asm volatile("st.shared.v4.b32 [%0], {%1,%2,%3,%4};" :: "r"(sb_lo + a),
                "r"(bl.x), "r"(bl.y), "r"(bl.z), "r"(bl.w) : "memory");
        }
    }
    __syncthreads();

    // --- warp grid 2(M) x 4(N): warp tile 64 x 32 ---
    int wm = (wid >> 2) * 64, wn = (wid & 3) * 32;
    float acc[4][4][4];
#pragma unroll
    for (int i = 0; i < 4; i++)
#pragma unroll
        for (int j = 0; j < 4; j++)
#pragma unroll
            for (int q = 0; q < 4; q++) acc[i][j][q] = 0.f;

    // ldmatrix lane address components
    uint32_t aRow = (uint32_t)(wm + (lane & 15));        // + mi*16
    uint32_t aKof = (uint32_t)((lane >> 4) * 8);
    uint32_t bRow = (uint32_t)(wn + (lane & 7) + ((lane >> 4) << 3)); // + nb*16
    uint32_t bKof = (uint32_t)(((lane >> 3) & 1) * 8);

#pragma unroll
    for (int ks = 0; ks < 8; ks++) {
        int k0 = ks * 16;
        uint32_t ah[4][4], al[4][4], bh[2][4], bl[2][4];
#pragma unroll
        for (int mi = 0; mi < 4; mi++) {
            uint32_t a = (uint32_t)((aRow + mi * 16) * SPAD + k0 + aKof) * 2;
            LDSM_X4(ah[mi][0], ah[mi][1], ah[mi][2], ah[mi][3], sa_hi + a);
            LDSM_X4(al[mi][0], al[mi][1], al[mi][2], al[mi][3], sa_lo + a);
        }
#pragma unroll
        for (int nb = 0; nb < 2; nb++) {
            uint32_t a = (uint32_t)((bRow + nb * 16) * SPAD + k0 + bKof) * 2;
            LDSM_X4(bh[nb][0], bh[nb][1], bh[nb][2], bh[nb][3], sb_hi + a);
            LDSM_X4(bl[nb][0], bl[nb][1], bl[nb][2], bl[nb][3], sb_lo + a);
        }
#pragma unroll
        for (int mi = 0; mi < 4; mi++)
#pragma unroll
            for (int nj = 0; nj < 4; nj++) {
                int nb = nj >> 1, bo = (nj & 1) * 2;
                MMA16816(acc[mi][nj], ah[mi], bh[nb][bo], bh[nb][bo + 1]); // hi*hi
                MMA16816(acc[mi][nj], ah[mi], bl[nb][bo], bl[nb][bo + 1]); // hi*lo
                MMA16816(acc[mi][nj], al[mi], bh[nb][bo], bh[nb][bo + 1]); // lo*hi
            }
    }

    // --- epilogue: fragment -> global float2 stores ---
    int crow0 = blockIdx.y * 128 + wm + (lane >> 2);
    int ccol0 = blockIdx.x * 128 + wn + (lane & 3) * 2;
#pragma unroll
    for (int mi = 0; mi < 4; mi++) {
#pragma unroll
        for (int nj = 0; nj < 4; nj++) {
            int r0 = crow0 + mi * 16;
            int cc = ccol0 + nj * 8;
            if (r0 < M)
                *(float2*)(C + (size_t)r0 * ldc + cc) = make_float2(acc[mi][nj][0], acc[mi][nj][1]);
            if (r0 + 8 < M)
                *(float2*)(C + (size_t)(r0 + 8) * ldc + cc) = make_float2(acc[mi][nj][2], acc[mi][nj][3]);
        }
    }
}

// ---------------- pull-mode mean aggregation ---------------------------------
__global__ void k_agg1(const float* __restrict__ b1) {
    int gt = blockIdx.x * blockDim.x + threadIdx.x;
    int w = gt >> 5, lane = gt & 31;
    if (w >= NN) return;
    int start = g_rowptr[w], deg = g_deg[w];
    float4 acc = make_float4(0.f, 0.f, 0.f, 0.f);
    for (int e = 0; e < deg; e++) {
        int s = g_csr[start + e];
        float4 v = *(const float4*)(g_z1 + (size_t)s * 256 + lane * 4);
        acc.x += v.x; acc.y += v.y; acc.z += v.z; acc.w += v.w;
    }
    float inv = 1.f / (float)(deg > 0 ? deg : 1);
    float4 r  = *(const float4*)(g_z1 + (size_t)w * 256 + 128 + lane * 4);
    float4 bb = *(const float4*)(b1 + lane * 4);
    float4 o;
    o.x = fmaxf(fmaf(acc.x, inv, bb.x + r.x), 0.f);
    o.y = fmaxf(fmaf(acc.y, inv, bb.y + r.y), 0.f);
    o.z = fmaxf(fmaf(acc.z, inv, bb.z + r.z), 0.f);
    o.w = fmaxf(fmaf(acc.w, inv, bb.w + r.w), 0.f);
    *(float4*)(g_h + (size_t)w * 128 + lane * 4) = o;
}

__global__ void k_agg2(const float* __restrict__ b2, float* __restrict__ out) {
    int gt = blockIdx.x * blockDim.x + threadIdx.x;
    int w = gt >> 5, lane = gt & 31;
    if (w >= NN) return;
    int start = g_rowptr[w], deg = g_deg[w];
    float2 acc = make_float2(0.f, 0.f);
    for (int e = 0; e < deg; e++) {
        int s = g_csr[start + e];
        float2 v = *(const float2*)(g_z2 + (size_t)s * 128 + lane * 2);
        acc.x += v.x; acc.y += v.y;
    }
    float inv = 1.f / (float)(deg > 0 ? deg : 1);
    float2 r = *(const float2*)(g_z2 + (size_t)w * 128 + 64 + lane * 2);
    float2 o;
    o.x = fmaf(acc.x, inv, b2[lane * 2 + 0] + r.x);
    o.y = fmaf(acc.y, inv, b2[lane * 2 + 1] + r.y);
    *(float2*)(out + (size_t)w * 64 + lane * 2) = o;
}

// ---------------- launch ------------------------------------------------------
extern "C" void kernel_launch(void* const* d_in, const int* in_sizes, int n_in,
                              void* d_out, int out_size)
{
    const float* x   = (const float*)d_in[0];
    const int*   ei  = (const int*)d_in[1];
    const float* W1l = (const float*)d_in[2];
    const float* b1  = (const float*)d_in[3];
    const float* W1r = (const float*)d_in[4];
    const float* W2l = (const float*)d_in[5];
    const float* b2  = (const float*)d_in[6];
    const float* W2r = (const float*)d_in[7];
    float* out = (float*)d_out;
    const int* src = ei;
    const int* dst = ei + NE;

    float *z1, *h, *z2;
    __nv_bfloat16 *w1h, *w1l, *w2h, *w2l;
    cudaGetSymbolAddress((void**)&z1,  g_z1);
    cudaGetSymbolAddress((void**)&h,   g_h);
    cudaGetSymbolAddress((void**)&z2,  g_z2);
    cudaGetSymbolAddress((void**)&w1h, g_w1h);
    cudaGetSymbolAddress((void**)&w1l, g_w1l);
    cudaGetSymbolAddress((void**)&w2h, g_w2h);
    cudaGetSymbolAddress((void**)&w2l, g_w2l);

    cudaFuncSetAttribute(k_gemm_mma, cudaFuncAttributeMaxDynamicSharedMemorySize, SMEM_TOT);

    // weight prep
    k_prep_w1<<<(256 * 128 + 255) / 256, 256>>>(W1l, W1r);
    k_prep_w2<<<(128 * 128 + 255) / 256, 256>>>(W2l, W2r);

    // CSR build
    k_zero_deg<<<(NN + 255) / 256, 256>>>();
    k_hist<<<(NE + 255) / 256, 256>>>(dst);
    int nb = (NN + 1023) / 1024;
    k_scan1<<<nb, 1024>>>();
    k_scan2<<<1, 32>>>(nb);
    k_scan3<<<(NN + 255) / 256, 256>>>();
    k_fill<<<(NE + 255) / 256, 256>>>(src, dst);

    int mtiles = (NN + 127) / 128;

    // layer 1: z1 = x @ [W1l | W1r], then pull-mean + bias + relu
    k_gemm_mma<<<dim3(2, mtiles), 256, SMEM_TOT>>>(x, NN, 256, w1h, w1l, z1);
    k_agg1<<<(NN * 32 + 255) / 256, 256>>>(b1);

    // layer 2: z2 = h @ [W2l | W2r], then pull-mean + bias
    k_gemm_mma<<<dim3(1, mtiles), 256, SMEM_TOT>>>(h, NN, 128, w2h, w2l, z2);
    k_agg2<<<(NN * 32 + 255) / 256, 256>>>(b2, out);
}

// round 7
// speedup vs baseline: 1.3517x; 1.0867x over previous
#include <cuda_runtime.h>
#include <cuda_bf16.h>
#include <cuda_fp16.h>
#include <cstdint>

#define NN 100000
#define NE 1600000

// ---------------- scratch (device globals; no allocation allowed) -------------
__device__ __half g_z1h[(size_t)NN * 128]; // x@W1l (aggregated half)  fp16
__device__ float  g_z1r[(size_t)NN * 128]; // x@W1r (root half)        fp32
__device__ float  g_h  [(size_t)NN * 128]; // relu(layer1)
__device__ __half g_z2h[(size_t)NN * 64];  // h@W2l                    fp16
__device__ float  g_z2r[(size_t)NN * 64];  // h@W2r                    fp32
__device__ __nv_bfloat16 g_w1h[256 * 128]; // W1 concat, transposed [h',d], hi
__device__ __nv_bfloat16 g_w1l[256 * 128]; // lo
__device__ __nv_bfloat16 g_w2h[128 * 128];
__device__ __nv_bfloat16 g_w2l[128 * 128];
__device__ int   g_deg[NN];
__device__ int   g_rowptr[NN];
__device__ int   g_pos[NN];
__device__ int   g_csr[NE];
__device__ int   g_bsum[128];

// ---------------- helpers ------------------------------------------------------
__device__ __forceinline__ uint32_t smem_u32(const void* p) {
    uint32_t a;
    asm("{ .reg .u64 t; cvta.to.shared.u64 t, %1; cvt.u32.u64 %0, t; }" : "=r"(a) : "l"(p));
    return a;
}
#define LDSM_X4(r0, r1, r2, r3, a) \
    asm volatile("ldmatrix.sync.aligned.m8n8.x4.shared.b16 {%0,%1,%2,%3}, [%4];" \
        : "=r"(r0), "=r"(r1), "=r"(r2), "=r"(r3) : "r"(a))
#define MMA16816(c, a, b0, b1) \
    asm volatile("mma.sync.aligned.m16n8k16.row.col.f32.bf16.bf16.f32 " \
        "{%0,%1,%2,%3}, {%4,%5,%6,%7}, {%8,%9}, {%0,%1,%2,%3};" \
        : "+f"((c)[0]), "+f"((c)[1]), "+f"((c)[2]), "+f"((c)[3]) \
        : "r"((a)[0]), "r"((a)[1]), "r"((a)[2]), "r"((a)[3]), "r"(b0), "r"(b1))

// ---------------- fused init: weight prep + zero deg --------------------------
__global__ void k_init(const float* __restrict__ W1l, const float* __restrict__ W1r,
                       const float* __restrict__ W2l, const float* __restrict__ W2r) {
    int i = blockIdx.x * 256 + threadIdx.x;
    if (i < 256 * 128) {                       // w1 prep: i = hp*128 + d
        int hp = i >> 7, d = i & 127;
        float v = (hp < 128) ? W1l[d * 128 + hp] : W1r[d * 128 + (hp - 128)];
        __nv_bfloat16 h = __float2bfloat16(v);
        g_w1h[i] = h;
        g_w1l[i] = __float2bfloat16(v - __bfloat162float(h));
    }
    if (i < 128 * 128) {                       // w2 prep: i = op*128 + k
        int op = i >> 7, k = i & 127;
        float v = (op < 64) ? W2l[k * 64 + op] : W2r[k * 64 + (op - 64)];
        __nv_bfloat16 h = __float2bfloat16(v);
        g_w2h[i] = h;
        g_w2l[i] = __float2bfloat16(v - __bfloat162float(h));
    }
    if (i < NN) g_deg[i] = 0;
}

// ---------------- CSR build ---------------------------------------------------
__global__ void k_hist(const int* __restrict__ dst) {
    int e = blockIdx.x * 256 + threadIdx.x;
    if (e < NE) atomicAdd(&g_deg[dst[e]], 1);
}
__global__ void k_scan1() {
    __shared__ int sm[1024];
    int t = threadIdx.x;
    int i = blockIdx.x * 1024 + t;
    int v = (i < NN) ? g_deg[i] : 0;
    sm[t] = v;
    __syncthreads();
    for (int off = 1; off < 1024; off <<= 1) {
        int tmp = (t >= off) ? sm[t - off] : 0;
        __syncthreads();
        sm[t] += tmp;
        __syncthreads();
    }
    if (i < NN) g_rowptr[i] = sm[t] - v;
    if (t == 1023) g_bsum[blockIdx.x] = sm[1023];
}
__global__ void k_scan2(int nb) {
    if (threadIdx.x == 0) {
        int acc = 0;
        for (int b = 0; b < nb; b++) { int tv = g_bsum[b]; g_bsum[b] = acc; acc += tv; }
    }
}
__global__ void k_scan3() {
    int i = blockIdx.x * 256 + threadIdx.x;
    if (i < NN) {
        int v = g_rowptr[i] + g_bsum[i >> 10];
        g_rowptr[i] = v;
        g_pos[i]    = v;
    }
}
__global__ void k_fill(const int* __restrict__ src, const int* __restrict__ dst) {
    int e = blockIdx.x * 256 + threadIdx.x;
    if (e < NE) {
        int idx = atomicAdd(&g_pos[dst[e]], 1);
        g_csr[idx] = src[e];
    }
}

// ---------------- mma.sync split-bf16 GEMM ------------------------------------
// A[M x 128] fp32 * B^T (bf16 hi/lo). Output columns < split -> fp16 buffer Ch,
// columns >= split -> fp32 buffer Cf (col - split). split is a multiple of 32
// so each warp (32-col tile) is entirely on one side.
#define SPAD   136
#define SMATB  (128 * SPAD * 2)
#define SMEM_TOT (4 * SMATB)

__global__ __launch_bounds__(256, 1) void k_gemm_mma(
    const float* __restrict__ A, int M,
    __half* __restrict__ Ch, int ldh,
    float* __restrict__ Cf, int ldf, int split,
    const __nv_bfloat16* __restrict__ Bh, const __nv_bfloat16* __restrict__ Bl)
{
    extern __shared__ __align__(16) char smem[];
    uint32_t s0 = smem_u32(smem);
    const uint32_t sa_hi = s0, sa_lo = s0 + SMATB;
    const uint32_t sb_hi = s0 + 2 * SMATB, sb_lo = s0 + 3 * SMATB;

    int tid = threadIdx.x, lane = tid & 31, wid = tid >> 5;
    int row = tid >> 1, half = tid & 1;

    // --- A tile: fp32 -> bf16 hi/lo -> padded smem ---
    {
        int gRow = blockIdx.y * 128 + row;
        bool valid = gRow < M;
        const float4* Ar = (const float4*)(A + (size_t)gRow * 128 + half * 64);
        uint32_t base = (uint32_t)(row * SPAD + half * 64) * 2;
#pragma unroll
        for (int j = 0; j < 8; j++) {
            float4 v0 = make_float4(0.f, 0.f, 0.f, 0.f), v1 = v0;
            if (valid) { v0 = Ar[j * 2]; v1 = Ar[j * 2 + 1]; }
            float2 p[4] = {{v0.x, v0.y}, {v0.z, v0.w}, {v1.x, v1.y}, {v1.z, v1.w}};
            uint32_t hw[4], lw[4];
#pragma unroll
            for (int q = 0; q < 4; q++) {
                __nv_bfloat162 hh = __floats2bfloat162_rn(p[q].x, p[q].y);
                float2 hf = __bfloat1622float2(hh);
                __nv_bfloat162 ll = __floats2bfloat162_rn(p[q].x - hf.x, p[q].y - hf.y);
                hw[q] = *(uint32_t*)&hh;
                lw[q] = *(uint32_t*)&ll;
            }
            uint32_t a = base + j * 16;
            asm volatile("st.shared.v4.b32 [%0], {%1,%2,%3,%4};" :: "r"(sa_hi + a),
                "r"(hw[0]), "r"(hw[1]), "r"(hw[2]), "r"(hw[3]) : "memory");
            asm volatile("st.shared.v4.b32 [%0], {%1,%2,%3,%4};" :: "r"(sa_lo + a),
                "r"(lw[0]), "r"(lw[1]), "r"(lw[2]), "r"(lw[3]) : "memory");
        }
    }
    // --- B tile: bf16 hi/lo from global -> padded smem ---
    {
        size_t nRow = (size_t)(blockIdx.x * 128 + row);
        const uint4* Bhr = (const uint4*)(Bh + nRow * 128 + half * 64);
        const uint4* Blr = (const uint4*)(Bl + nRow * 128 + half * 64);
        uint32_t base = (uint32_t)(row * SPAD + half * 64) * 2;
#pragma unroll
        for (int j = 0; j < 8; j++) {
            uint4 bh = Bhr[j], bl = Blr[j];
            uint32_t a = base + j * 16;
            asm volatile("st.shared.v4.b32 [%0], {%1,%2,%3,%4};" :: "r"(sb_hi + a),
                "r"(bh.x), "r"(bh.y), "r"(bh.z), "r"(bh.w) : "memory");
            asm volatile("st.shared.v4.b32 [%0], {%1,%2,%3,%4};" :: "r"(sb_lo + a),
                "r"(bl.x), "r"(bl.y), "r"(bl.z), "r"(bl.w) : "memory");
        }
    }
    __syncthreads();

    // --- warp grid 2(M) x 4(N): warp tile 64 x 32 ---
    int wm = (wid >> 2) * 64, wn = (wid & 3) * 32;
    float acc[4][4][4];
#pragma unroll
    for (int i = 0; i < 4; i++)
#pragma unroll
        for (int j = 0; j < 4; j++)
#pragma unroll
            for (int q = 0; q < 4; q++) acc[i][j][q] = 0.f;

    uint32_t aRow = (uint32_t)(wm + (lane & 15));
    uint32_t aKof = (uint32_t)((lane >> 4) * 8);
    uint32_t bRow = (uint32_t)(wn + (lane & 7) + ((lane >> 4) << 3));
    uint32_t bKof = (uint32_t)(((lane >> 3) & 1) * 8);

#pragma unroll
    for (int ks = 0; ks < 8; ks++) {
        int k0 = ks * 16;
        uint32_t ah[4][4], al[4][4], bh[2][4], bl[2][4];
#pragma unroll
        for (int mi = 0; mi < 4; mi++) {
            uint32_t a = (uint32_t)((aRow + mi * 16) * SPAD + k0 + aKof) * 2;
            LDSM_X4(ah[mi][0], ah[mi][1], ah[mi][2], ah[mi][3], sa_hi + a);
            LDSM_X4(al[mi][0], al[mi][1], al[mi][2], al[mi][3], sa_lo + a);
        }
#pragma unroll
        for (int nb = 0; nb < 2; nb++) {
            uint32_t a = (uint32_t)((bRow + nb * 16) * SPAD + k0 + bKof) * 2;
            LDSM_X4(bh[nb][0], bh[nb][1], bh[nb][2], bh[nb][3], sb_hi + a);
            LDSM_X4(bl[nb][0], bl[nb][1], bl[nb][2], bl[nb][3], sb_lo + a);
        }
#pragma unroll
        for (int mi = 0; mi < 4; mi++)
#pragma unroll
            for (int nj = 0; nj < 4; nj++) {
                int nb = nj >> 1, bo = (nj & 1) * 2;
                MMA16816(acc[mi][nj], ah[mi], bh[nb][bo], bh[nb][bo + 1]);
                MMA16816(acc[mi][nj], ah[mi], bl[nb][bo], bl[nb][bo + 1]);
                MMA16816(acc[mi][nj], al[mi], bh[nb][bo], bh[nb][bo + 1]);
            }
    }

    // --- epilogue: left cols -> fp16 buffer, right cols -> fp32 buffer ---
    int gcolw = blockIdx.x * 128 + wn;          // warp's global col base
    bool leftw = gcolw < split;
    int crow0 = blockIdx.y * 128 + wm + (lane >> 2);
    int ccol0 = gcolw + (lane & 3) * 2;
#pragma unroll
    for (int mi = 0; mi < 4; mi++) {
#pragma unroll
        for (int nj = 0; nj < 4; nj++) {
            int r0 = crow0 + mi * 16;
            int cc = ccol0 + nj * 8;
            if (leftw) {
                __half2 v01 = __floats2half2_rn(acc[mi][nj][0], acc[mi][nj][1]);
                __half2 v23 = __floats2half2_rn(acc[mi][nj][2], acc[mi][nj][3]);
                if (r0 < M)     *(__half2*)(Ch + (size_t)r0 * ldh + cc) = v01;
                if (r0 + 8 < M) *(__half2*)(Ch + (size_t)(r0 + 8) * ldh + cc) = v23;
            } else {
                int cf = cc - split;
                if (r0 < M)
                    *(float2*)(Cf + (size_t)r0 * ldf + cf) = make_float2(acc[mi][nj][0], acc[mi][nj][1]);
                if (r0 + 8 < M)
                    *(float2*)(Cf + (size_t)(r0 + 8) * ldf + cf) = make_float2(acc[mi][nj][2], acc[mi][nj][3]);
            }
        }
    }
}

// ---------------- pull-mode mean aggregation (fp16 gather) --------------------
// layer 1: h[i] = relu( mean_j z1h[j,:] + b1 + z1r[i,:] )
__global__ void k_agg1(const float* __restrict__ b1) {
    int gt = blockIdx.x * blockDim.x + threadIdx.x;
    int w = gt >> 5, lane = gt & 31;
    if (w >= NN) return;
    int start = g_rowptr[w], deg = g_deg[w];
    float4 acc = make_float4(0.f, 0.f, 0.f, 0.f);
    for (int e = 0; e < deg; e++) {
        int s = g_csr[start + e];
        uint2 u = *(const uint2*)(g_z1h + (size_t)s * 128 + lane * 4);
        float2 a = __half22float2(*(__half2*)&u.x);
        float2 b = __half22float2(*(__half2*)&u.y);
        acc.x += a.x; acc.y += a.y; acc.z += b.x; acc.w += b.y;
    }
    float inv = 1.f / (float)(deg > 0 ? deg : 1);
    float4 r  = *(const float4*)(g_z1r + (size_t)w * 128 + lane * 4);
    float4 bb = *(const float4*)(b1 + lane * 4);
    float4 o;
    o.x = fmaxf(fmaf(acc.x, inv, bb.x + r.x), 0.f);
    o.y = fmaxf(fmaf(acc.y, inv, bb.y + r.y), 0.f);
    o.z = fmaxf(fmaf(acc.z, inv, bb.z + r.z), 0.f);
    o.w = fmaxf(fmaf(acc.w, inv, bb.w + r.w), 0.f);
    *(float4*)(g_h + (size_t)w * 128 + lane * 4) = o;
}

// layer 2: out[i] = mean_j z2h[j,:] + b2 + z2r[i,:]
__global__ void k_agg2(const float* __restrict__ b2, float* __restrict__ out) {
    int gt = blockIdx.x * blockDim.x + threadIdx.x;
    int w = gt >> 5, lane = gt & 31;
    if (w >= NN) return;
    int start = g_rowptr[w], deg = g_deg[w];
    float2 acc = make_float2(0.f, 0.f);
    for (int e = 0; e < deg; e++) {
        int s = g_csr[start + e];
        uint32_t u = *(const uint32_t*)(g_z2h + (size_t)s * 64 + lane * 2);
        float2 a = __half22float2(*(__half2*)&u);
        acc.x += a.x; acc.y += a.y;
    }
    float inv = 1.f / (float)(deg > 0 ? deg : 1);
    float2 r = *(const float2*)(g_z2r + (size_t)w * 64 + lane * 2);
    float2 o;
    o.x = fmaf(acc.x, inv, b2[lane * 2 + 0] + r.x);
    o.y = fmaf(acc.y, inv, b2[lane * 2 + 1] + r.y);
    *(float2*)(out + (size_t)w * 64 + lane * 2) = o;
}

// ---------------- launch ------------------------------------------------------
extern "C" void kernel_launch(void* const* d_in, const int* in_sizes, int n_in,
                              void* d_out, int out_size)
{
    const float* x   = (const float*)d_in[0];
    const int*   ei  = (const int*)d_in[1];
    const float* W1l = (const float*)d_in[2];
    const float* b1  = (const float*)d_in[3];
    const float* W1r = (const float*)d_in[4];
    const float* W2l = (const float*)d_in[5];
    const float* b2  = (const float*)d_in[6];
    const float* W2r = (const float*)d_in[7];
    float* out = (float*)d_out;
    const int* src = ei;
    const int* dst = ei + NE;

    float *z1r, *h, *z2r;
    __half *z1h, *z2h;
    __nv_bfloat16 *w1h, *w1l, *w2h, *w2l;
    cudaGetSymbolAddress((void**)&z1h, g_z1h);
    cudaGetSymbolAddress((void**)&z1r, g_z1r);
    cudaGetSymbolAddress((void**)&h,   g_h);
    cudaGetSymbolAddress((void**)&z2h, g_z2h);
    cudaGetSymbolAddress((void**)&z2r, g_z2r);
    cudaGetSymbolAddress((void**)&w1h, g_w1h);
    cudaGetSymbolAddress((void**)&w1l, g_w1l);
    cudaGetSymbolAddress((void**)&w2h, g_w2h);
    cudaGetSymbolAddress((void**)&w2l, g_w2l);

    cudaFuncSetAttribute(k_gemm_mma, cudaFuncAttributeMaxDynamicSharedMemorySize, SMEM_TOT);

    // fused init: weight prep + deg zero
    k_init<<<(NN + 255) / 256, 256>>>(W1l, W1r, W2l, W2r);

    // CSR build
    k_hist<<<(NE + 255) / 256, 256>>>(dst);
    int nb = (NN + 1023) / 1024;
    k_scan1<<<nb, 1024>>>();
    k_scan2<<<1, 32>>>(nb);
    k_scan3<<<(NN + 255) / 256, 256>>>();
    k_fill<<<(NE + 255) / 256, 256>>>(src, dst);

    int mtiles = (NN + 127) / 128;

    // layer 1: z1 = x @ [W1l | W1r]  (left->fp16, right->fp32), pull-mean+relu
    k_gemm_mma<<<dim3(2, mtiles), 256, SMEM_TOT>>>(x, NN, z1h, 128, z1r, 128, 128, w1h, w1l);
    k_agg1<<<(NN * 32 + 255) / 256, 256>>>(b1);

    // layer 2: z2 = h @ [W2l | W2r]  (left->fp16, right->fp32), pull-mean
    k_gemm_mma<<<dim3(1, mtiles), 256, SMEM_TOT>>>(h, NN, z2h, 64, z2r, 64, 64, w2h, w2l);
    k_agg2<<<(NN * 32 + 255) / 256, 256>>>(b2, out);
}